// round 1
// baseline (speedup 1.0000x reference)
#include <cuda_runtime.h>
#include <cuda_bf16.h>

#define NMAX (1 << 20)   // >= 1,000,000 nodes
#define BMAX 512         // >= 256 graphs
#define NPB  2048        // nodes per block in k_out

// Scratch (static device globals; no allocation anywhere)
__device__ float g_e[NMAX];
__device__ float g_alpha[NMAX];
__device__ float g_qry[BMAX * 128];
__device__ float g_m[BMAX];
__device__ float g_denom[BMAX];

// ---------------------------------------------------------------------------
// helpers
// ---------------------------------------------------------------------------
__device__ __forceinline__ unsigned f2tf(float x) {
    unsigned u;
    asm("cvt.rna.tf32.f32 %0, %1;" : "=r"(u) : "f"(x));
    return u;
}

__device__ __forceinline__ void mma_tf32(float* c, const unsigned* a, const unsigned* b) {
    asm volatile(
        "mma.sync.aligned.m16n8k8.row.col.f32.tf32.tf32.f32 "
        "{%0,%1,%2,%3}, {%4,%5,%6,%7}, {%8,%9}, {%0,%1,%2,%3};"
        : "+f"(c[0]), "+f"(c[1]), "+f"(c[2]), "+f"(c[3])
        : "r"(a[0]), "r"(a[1]), "r"(a[2]), "r"(a[3]),
          "r"(b[0]), "r"(b[1]));
}

// ---------------------------------------------------------------------------
// 1) qry[b,d] = feat_u[b,:] @ W_user[:,d] + b_user[d]
// ---------------------------------------------------------------------------
__global__ void k_qry(const float* __restrict__ feat_u,
                      const float* __restrict__ W_user,
                      const float* __restrict__ b_user) {
    __shared__ float su[128];
    int b = blockIdx.x, d = threadIdx.x;
    su[d] = feat_u[b * 128 + d];
    __syncthreads();
    float acc = b_user[d];
#pragma unroll 8
    for (int k = 0; k < 128; ++k)
        acc += su[k] * W_user[k * 128 + d];
    g_qry[b * 128 + d] = acc;
}

// ---------------------------------------------------------------------------
// 2) e[n] = sum_d sigmoid(qry[seg[n],d] + (feat_i @ W_key)[n,d]) * W_e[d]
//    Fused tf32 mma.sync GEMM; key never hits memory.
//    Block = 256 threads = 8 warps; warp handles 32 nodes (2 m16 tiles).
//    N (=128 cols of key) processed in 2 chunks of 64 (8 n8 tiles).
// ---------------------------------------------------------------------------
__global__ __launch_bounds__(256) void k_e(const float* __restrict__ feat_i,
                                           const int* __restrict__ seg,
                                           const float* __restrict__ W_key,
                                           const float* __restrict__ W_e,
                                           int N) {
    const int lane = threadIdx.x & 31;
    const int w    = threadIdx.x >> 5;
    const int g    = lane >> 2;   // groupID (row within tile)
    const int qr   = lane & 3;    // threadID_in_group
    const int base = blockIdx.x * 256 + w * 32;
    if (base >= N) return;

    // seg per (m-tile, row-half): row = base + mt*16 + h*8 + g
    int sidx[4];
    float epart[4] = {0.f, 0.f, 0.f, 0.f};
#pragma unroll
    for (int mt = 0; mt < 2; ++mt)
#pragma unroll
        for (int h = 0; h < 2; ++h) {
            int r = base + mt * 16 + h * 8 + g;
            sidx[mt * 2 + h] = (r < N) ? seg[r] : 0;
        }

#pragma unroll
    for (int c = 0; c < 2; ++c) {
        float acc[2][8][4];
#pragma unroll
        for (int mt = 0; mt < 2; ++mt)
#pragma unroll
            for (int nt = 0; nt < 8; ++nt)
#pragma unroll
                for (int i = 0; i < 4; ++i)
                    acc[mt][nt][i] = 0.f;

#pragma unroll 4
        for (int k = 0; k < 16; ++k) {
            unsigned A[2][4];
#pragma unroll
            for (int mt = 0; mt < 2; ++mt) {
                int r0 = base + mt * 16 + g;
                int r1 = r0 + 8;
                int c0 = k * 8 + qr;
                A[mt][0] = f2tf(r0 < N ? feat_i[r0 * 128 + c0]     : 0.f);
                A[mt][1] = f2tf(r1 < N ? feat_i[r1 * 128 + c0]     : 0.f);
                A[mt][2] = f2tf(r0 < N ? feat_i[r0 * 128 + c0 + 4] : 0.f);
                A[mt][3] = f2tf(r1 < N ? feat_i[r1 * 128 + c0 + 4] : 0.f);
            }
            unsigned Bf[8][2];
            int kr = k * 8 + qr;
#pragma unroll
            for (int nt = 0; nt < 8; ++nt) {
                int nc = c * 64 + nt * 8 + g;
                Bf[nt][0] = f2tf(W_key[kr * 128 + nc]);
                Bf[nt][1] = f2tf(W_key[(kr + 4) * 128 + nc]);
            }
#pragma unroll
            for (int mt = 0; mt < 2; ++mt)
#pragma unroll
                for (int nt = 0; nt < 8; ++nt)
                    mma_tf32(acc[mt][nt], A[mt], Bf[nt]);
        }

        // fold this chunk's key columns into scalar e partials
#pragma unroll
        for (int mt = 0; mt < 2; ++mt)
#pragma unroll
            for (int nt = 0; nt < 8; ++nt)
#pragma unroll
                for (int i = 0; i < 4; ++i) {
                    int col  = c * 64 + nt * 8 + 2 * qr + (i & 1);
                    int slot = mt * 2 + (i >> 1);
                    float q  = g_qry[sidx[slot] * 128 + col];
                    float x  = q + acc[mt][nt][i];
                    float sg = 1.f / (1.f + __expf(-x));
                    epart[slot] += sg * __ldg(&W_e[col]);
                }
    }

    // reduce across the 4 lanes of each quad (same row)
#pragma unroll
    for (int j = 0; j < 4; ++j) {
        epart[j] += __shfl_xor_sync(0xffffffffu, epart[j], 1);
        epart[j] += __shfl_xor_sync(0xffffffffu, epart[j], 2);
    }
    if (qr == 0) {
#pragma unroll
        for (int j = 0; j < 4; ++j) {
            int r = base + (j >> 1) * 16 + (j & 1) * 8 + g;
            if (r < N) g_e[r] = epart[j];
        }
    }
}

// ---------------------------------------------------------------------------
// 3) per-segment max and sum(exp(e-m)); seg is sorted -> binary search bounds
// ---------------------------------------------------------------------------
__global__ void k_seg(const int* __restrict__ seg, int N) {
    int b = blockIdx.x, tid = threadIdx.x;
    int lo = 0, hi = N;
    while (lo < hi) { int mid = (lo + hi) >> 1; if (seg[mid] < b) lo = mid + 1; else hi = mid; }
    int s0 = lo;
    hi = N;
    while (lo < hi) { int mid = (lo + hi) >> 1; if (seg[mid] < b + 1) lo = mid + 1; else hi = mid; }
    int s1 = lo;

    __shared__ float red[8];
    float mx = -3.402823466e38f;
    for (int i = s0 + tid; i < s1; i += 256) mx = fmaxf(mx, g_e[i]);
#pragma unroll
    for (int o = 16; o; o >>= 1) mx = fmaxf(mx, __shfl_xor_sync(~0u, mx, o));
    if ((tid & 31) == 0) red[tid >> 5] = mx;
    __syncthreads();
    if (tid == 0) {
        float v = red[0];
#pragma unroll
        for (int i = 1; i < 8; ++i) v = fmaxf(v, red[i]);
        red[0] = v;
    }
    __syncthreads();
    float m = red[0];
    __syncthreads();

    float sm = 0.f;
    for (int i = s0 + tid; i < s1; i += 256) sm += __expf(g_e[i] - m);
#pragma unroll
    for (int o = 16; o; o >>= 1) sm += __shfl_xor_sync(~0u, sm, o);
    if ((tid & 31) == 0) red[tid >> 5] = sm;
    __syncthreads();
    if (tid == 0) {
        float t = 0.f;
#pragma unroll
        for (int i = 0; i < 8; ++i) t += red[i];
        g_m[b]     = (s1 > s0) ? m : 0.f;
        g_denom[b] = (s1 > s0) ? t : 1.f;
    }
}

// ---------------------------------------------------------------------------
// 4) alpha[n] = exp(e[n]-m[seg])/denom[seg]
// ---------------------------------------------------------------------------
__global__ void k_alpha(const int* __restrict__ seg, int N) {
    int i = blockIdx.x * 256 + threadIdx.x;
    if (i < N) {
        int s = seg[i];
        g_alpha[i] = __expf(g_e[i] - g_m[s]) / g_denom[s];
    }
}

// ---------------------------------------------------------------------------
// 5) rst[b,:] += alpha[n] * feat_i[n,:]; sorted seg -> rare atomic flushes
//    8 warps/block, each warp strided over rows; lane covers 4 cols (float4)
// ---------------------------------------------------------------------------
__global__ __launch_bounds__(256) void k_out(const float* __restrict__ feat_i,
                                             const int* __restrict__ seg,
                                             float* __restrict__ out, int N) {
    const int lane = threadIdx.x & 31;
    const int wj   = threadIdx.x >> 5;
    long start = (long)blockIdx.x * NPB;
    long end   = start + NPB;
    if (end > N) end = N;
    long n0 = start + wj;
    if (n0 >= end) return;

    float4 acc = make_float4(0.f, 0.f, 0.f, 0.f);
    int cur = seg[n0];
#pragma unroll 4
    for (long n = n0; n < end; n += 8) {
        int   s  = seg[n];
        float al = g_alpha[n];
        float4 v = *reinterpret_cast<const float4*>(&feat_i[n * 128 + lane * 4]);
        if (s != cur) {
            float* o = &out[cur * 128 + lane * 4];
            atomicAdd(o + 0, acc.x); atomicAdd(o + 1, acc.y);
            atomicAdd(o + 2, acc.z); atomicAdd(o + 3, acc.w);
            acc = make_float4(0.f, 0.f, 0.f, 0.f);
            cur = s;
        }
        acc.x += al * v.x; acc.y += al * v.y;
        acc.z += al * v.z; acc.w += al * v.w;
    }
    float* o = &out[cur * 128 + lane * 4];
    atomicAdd(o + 0, acc.x); atomicAdd(o + 1, acc.y);
    atomicAdd(o + 2, acc.z); atomicAdd(o + 3, acc.w);
}

// ---------------------------------------------------------------------------
extern "C" void kernel_launch(void* const* d_in, const int* in_sizes, int n_in,
                              void* d_out, int out_size) {
    const float* feat_i = (const float*)d_in[0];
    const float* feat_u = (const float*)d_in[1];
    const int*   seg    = (const int*)d_in[2];
    const float* W_key  = (const float*)d_in[3];
    const float* W_user = (const float*)d_in[4];
    const float* b_user = (const float*)d_in[5];
    const float* W_e    = (const float*)d_in[6];
    float* out = (float*)d_out;

    int N = in_sizes[0] / 128;
    int B = in_sizes[1] / 128;

    k_qry<<<B, 128>>>(feat_u, W_user, b_user);
    k_e<<<(N + 255) / 256, 256>>>(feat_i, seg, W_key, W_e, N);
    k_seg<<<B, 256>>>(seg, N);
    k_alpha<<<(N + 255) / 256, 256>>>(seg, N);
    cudaMemsetAsync(d_out, 0, (size_t)out_size * sizeof(float), 0);
    k_out<<<(N + NPB - 1) / NPB, 256>>>(feat_i, seg, out, N);
}

// round 2
// speedup vs baseline: 1.1060x; 1.1060x over previous
#include <cuda_runtime.h>
#include <cuda_bf16.h>

#define NMAX (1 << 20)   // >= 1,000,000 nodes
#define BMAX 512         // >= 256 graphs
#define NPB  2048        // nodes per block in k_out
#define MBLK 256         // rows per block in k_e

// smem layout for k_e (words)
#define SW_STRIDE 136
#define SA_STRIDE 132
#define SW_WORDS  (128 * SW_STRIDE)            // 17408
#define SA_WORDS  (MBLK * SA_STRIDE)           // 33792
#define SMEM_E_BYTES ((SW_WORDS + SA_WORDS + 128) * 4)  // 205,312 B

// Scratch (static device globals; no allocation anywhere)
__device__ float g_e[NMAX];
__device__ float g_qry[BMAX * 128];
__device__ float g_m[BMAX];
__device__ float g_denom[BMAX];

// ---------------------------------------------------------------------------
// helpers
// ---------------------------------------------------------------------------
__device__ __forceinline__ unsigned f2tf(float x) {
    unsigned u;
    asm("cvt.rna.tf32.f32 %0, %1;" : "=r"(u) : "f"(x));
    return u;
}

__device__ __forceinline__ void mma_tf32(float* c, const unsigned* a, const unsigned* b) {
    asm volatile(
        "mma.sync.aligned.m16n8k8.row.col.f32.tf32.tf32.f32 "
        "{%0,%1,%2,%3}, {%4,%5,%6,%7}, {%8,%9}, {%0,%1,%2,%3};"
        : "+f"(c[0]), "+f"(c[1]), "+f"(c[2]), "+f"(c[3])
        : "r"(a[0]), "r"(a[1]), "r"(a[2]), "r"(a[3]),
          "r"(b[0]), "r"(b[1]));
}

// ---------------------------------------------------------------------------
// 1) qry[b,d] = feat_u[b,:] @ W_user[:,d] + b_user[d]
// ---------------------------------------------------------------------------
__global__ void k_qry(const float* __restrict__ feat_u,
                      const float* __restrict__ W_user,
                      const float* __restrict__ b_user) {
    __shared__ float su[128];
    int b = blockIdx.x, d = threadIdx.x;
    su[d] = feat_u[b * 128 + d];
    __syncthreads();
    float acc = b_user[d];
#pragma unroll 8
    for (int k = 0; k < 128; ++k)
        acc += su[k] * W_user[k * 128 + d];
    g_qry[b * 128 + d] = acc;
}

// ---------------------------------------------------------------------------
// 2) e[n] = sum_d sigmoid(qry[seg[n],d] + (feat_i @ W_key)[n,d]) * W_e[d]
//    smem-staged tf32 mma: W_key once per block (stride 136, conflict-free
//    B frags); each warp stages its own 32 rows of feat_i (stride 132,
//    conflict-free A frags). key never hits gmem.
// ---------------------------------------------------------------------------
__global__ __launch_bounds__(256, 1) void k_e(const float* __restrict__ feat_i,
                                              const int* __restrict__ seg,
                                              const float* __restrict__ W_key,
                                              const float* __restrict__ W_e,
                                              int N) {
    extern __shared__ unsigned smem_u[];
    unsigned* sW  = smem_u;                       // [128][136] tf32 W_key
    unsigned* sA  = smem_u + SW_WORDS;            // [256][132] tf32 feat_i tile
    float*    sWe = (float*)(smem_u + SW_WORDS + SA_WORDS);  // [128]

    const int tid  = threadIdx.x;
    const int lane = tid & 31;
    const int w    = tid >> 5;
    const int g    = lane >> 2;   // groupID
    const int qr   = lane & 3;    // thread in group
    const int blockBase = blockIdx.x * MBLK;
    const int base = blockBase + w * 32;          // this warp's first row

    // ---- stage W_key (tf32) + W_e, block-wide ----
    for (int i = tid; i < 128 * 128; i += 256) {
        int kr = i >> 7, nc = i & 127;
        sW[kr * SW_STRIDE + nc] = f2tf(W_key[i]);
    }
    if (tid < 128) sWe[tid] = W_e[tid];
    __syncthreads();

    // ---- each warp stages its own 32 rows of feat_i (tf32) ----
    {
        const float* src = feat_i + (size_t)base * 128;
        unsigned* dst = sA + w * 32 * SA_STRIDE;
        for (int i = lane; i < 32 * 32; i += 32) {   // 32 rows x 32 float4
            int r  = i >> 5;
            int cv = i & 31;
            float4 v = (base + r < N) ? *(const float4*)(src + r * 128 + cv * 4)
                                      : make_float4(0.f, 0.f, 0.f, 0.f);
            unsigned* d4 = dst + r * SA_STRIDE + cv * 4;
            d4[0] = f2tf(v.x); d4[1] = f2tf(v.y);
            d4[2] = f2tf(v.z); d4[3] = f2tf(v.w);
        }
        __syncwarp();
    }

    // seg per (m-tile, row-half)
    int sidx[4];
    float epart[4] = {0.f, 0.f, 0.f, 0.f};
#pragma unroll
    for (int mt = 0; mt < 2; ++mt)
#pragma unroll
        for (int h = 0; h < 2; ++h) {
            int r = base + mt * 16 + h * 8 + g;
            sidx[mt * 2 + h] = (r < N) ? seg[r] : 0;
        }

#pragma unroll
    for (int c = 0; c < 2; ++c) {
        float acc[2][8][4];
#pragma unroll
        for (int mt = 0; mt < 2; ++mt)
#pragma unroll
            for (int nt = 0; nt < 8; ++nt)
#pragma unroll
                for (int i = 0; i < 4; ++i)
                    acc[mt][nt][i] = 0.f;

#pragma unroll 4
        for (int k = 0; k < 16; ++k) {
            unsigned A[2][4];
#pragma unroll
            for (int mt = 0; mt < 2; ++mt) {
                int lr0 = w * 32 + mt * 16 + g;
                int lr1 = lr0 + 8;
                int c0  = k * 8 + qr;
                A[mt][0] = sA[lr0 * SA_STRIDE + c0];
                A[mt][1] = sA[lr1 * SA_STRIDE + c0];
                A[mt][2] = sA[lr0 * SA_STRIDE + c0 + 4];
                A[mt][3] = sA[lr1 * SA_STRIDE + c0 + 4];
            }
            unsigned Bf[8][2];
            int kr = k * 8 + qr;
#pragma unroll
            for (int nt = 0; nt < 8; ++nt) {
                int nc = c * 64 + nt * 8 + g;
                Bf[nt][0] = sW[kr * SW_STRIDE + nc];
                Bf[nt][1] = sW[(kr + 4) * SW_STRIDE + nc];
            }
#pragma unroll
            for (int mt = 0; mt < 2; ++mt)
#pragma unroll
                for (int nt = 0; nt < 8; ++nt)
                    mma_tf32(acc[mt][nt], A[mt], Bf[nt]);
        }

        // fold this chunk's key columns into scalar e partials
#pragma unroll
        for (int mt = 0; mt < 2; ++mt)
#pragma unroll
            for (int nt = 0; nt < 8; ++nt)
#pragma unroll
                for (int i = 0; i < 4; ++i) {
                    int col  = c * 64 + nt * 8 + 2 * qr + (i & 1);
                    int slot = mt * 2 + (i >> 1);
                    float q  = g_qry[sidx[slot] * 128 + col];
                    float x  = q + acc[mt][nt][i];
                    float sg = 1.f / (1.f + __expf(-x));
                    epart[slot] += sg * sWe[col];
                }
    }

    // reduce across the 4 lanes of each quad (same row)
#pragma unroll
    for (int j = 0; j < 4; ++j) {
        epart[j] += __shfl_xor_sync(0xffffffffu, epart[j], 1);
        epart[j] += __shfl_xor_sync(0xffffffffu, epart[j], 2);
    }
    if (qr == 0) {
#pragma unroll
        for (int j = 0; j < 4; ++j) {
            int r = base + (j >> 1) * 16 + (j & 1) * 8 + g;
            if (r < N) g_e[r] = epart[j];
        }
    }
}

// ---------------------------------------------------------------------------
// 3) per-segment max and sum(exp(e-m)); seg is sorted -> binary search bounds
// ---------------------------------------------------------------------------
__global__ void k_seg(const int* __restrict__ seg, int N) {
    int b = blockIdx.x, tid = threadIdx.x;
    int lo = 0, hi = N;
    while (lo < hi) { int mid = (lo + hi) >> 1; if (seg[mid] < b) lo = mid + 1; else hi = mid; }
    int s0 = lo;
    hi = N;
    while (lo < hi) { int mid = (lo + hi) >> 1; if (seg[mid] < b + 1) lo = mid + 1; else hi = mid; }
    int s1 = lo;

    __shared__ float red[8];
    float mx = -3.402823466e38f;
    for (int i = s0 + tid; i < s1; i += 256) mx = fmaxf(mx, g_e[i]);
#pragma unroll
    for (int o = 16; o; o >>= 1) mx = fmaxf(mx, __shfl_xor_sync(~0u, mx, o));
    if ((tid & 31) == 0) red[tid >> 5] = mx;
    __syncthreads();
    if (tid == 0) {
        float v = red[0];
#pragma unroll
        for (int i = 1; i < 8; ++i) v = fmaxf(v, red[i]);
        red[0] = v;
    }
    __syncthreads();
    float m = red[0];
    __syncthreads();

    float sm = 0.f;
    for (int i = s0 + tid; i < s1; i += 256) sm += __expf(g_e[i] - m);
#pragma unroll
    for (int o = 16; o; o >>= 1) sm += __shfl_xor_sync(~0u, sm, o);
    if ((tid & 31) == 0) red[tid >> 5] = sm;
    __syncthreads();
    if (tid == 0) {
        float t = 0.f;
#pragma unroll
        for (int i = 0; i < 8; ++i) t += red[i];
        g_m[b]     = (s1 > s0) ? m : 0.f;
        g_denom[b] = (s1 > s0) ? t : 1.f;
    }
}

// ---------------------------------------------------------------------------
// 4) rst[b,:] += alpha[n] * feat_i[n,:]; alpha computed inline.
//    sorted seg -> rare atomic flushes.
// ---------------------------------------------------------------------------
__global__ __launch_bounds__(256) void k_out(const float* __restrict__ feat_i,
                                             const int* __restrict__ seg,
                                             float* __restrict__ out, int N) {
    const int lane = threadIdx.x & 31;
    const int wj   = threadIdx.x >> 5;
    long start = (long)blockIdx.x * NPB;
    long end   = start + NPB;
    if (end > N) end = N;
    long n0 = start + wj;
    if (n0 >= end) return;

    float4 acc = make_float4(0.f, 0.f, 0.f, 0.f);
    int cur = seg[n0];
#pragma unroll 4
    for (long n = n0; n < end; n += 8) {
        int   s  = seg[n];
        float al = __expf(g_e[n] - g_m[s]) / g_denom[s];
        float4 v = *reinterpret_cast<const float4*>(&feat_i[n * 128 + lane * 4]);
        if (s != cur) {
            float* o = &out[cur * 128 + lane * 4];
            atomicAdd(o + 0, acc.x); atomicAdd(o + 1, acc.y);
            atomicAdd(o + 2, acc.z); atomicAdd(o + 3, acc.w);
            acc = make_float4(0.f, 0.f, 0.f, 0.f);
            cur = s;
        }
        acc.x += al * v.x; acc.y += al * v.y;
        acc.z += al * v.z; acc.w += al * v.w;
    }
    float* o = &out[cur * 128 + lane * 4];
    atomicAdd(o + 0, acc.x); atomicAdd(o + 1, acc.y);
    atomicAdd(o + 2, acc.z); atomicAdd(o + 3, acc.w);
}

// ---------------------------------------------------------------------------
extern "C" void kernel_launch(void* const* d_in, const int* in_sizes, int n_in,
                              void* d_out, int out_size) {
    const float* feat_i = (const float*)d_in[0];
    const float* feat_u = (const float*)d_in[1];
    const int*   seg    = (const int*)d_in[2];
    const float* W_key  = (const float*)d_in[3];
    const float* W_user = (const float*)d_in[4];
    const float* b_user = (const float*)d_in[5];
    const float* W_e    = (const float*)d_in[6];
    float* out = (float*)d_out;

    int N = in_sizes[0] / 128;
    int B = in_sizes[1] / 128;

    static int smem_set = 0;
    if (!smem_set) {
        cudaFuncSetAttribute(k_e, cudaFuncAttributeMaxDynamicSharedMemorySize,
                             SMEM_E_BYTES);
        smem_set = 1;
    }

    k_qry<<<B, 128>>>(feat_u, W_user, b_user);
    k_e<<<(N + MBLK - 1) / MBLK, 256, SMEM_E_BYTES>>>(feat_i, seg, W_key, W_e, N);
    k_seg<<<B, 256>>>(seg, N);
    cudaMemsetAsync(d_out, 0, (size_t)out_size * sizeof(float), 0);
    k_out<<<(N + NPB - 1) / NPB, 256>>>(feat_i, seg, out, N);
}

// round 4
// speedup vs baseline: 1.8078x; 1.6345x over previous
#include <cuda_runtime.h>
#include <cuda_bf16.h>
#include <cstdint>

#define NMAX (1 << 20)   // >= 1,000,000 nodes
#define BMAX 512         // >= 256 graphs
#define NPB  512         // nodes per block in k_out
#define EBLK 256         // rows per block in k_e

// k_e shared memory word layout
#define SW_STRIDE 136
#define SA_STRIDE 132
#define SW_OFF 0
#define SA_OFF 17408                 // 128*136
#define SWE_OFF 51200                // SA_OFF + 256*132
#define SE_OFF 51328                 // SWE_OFF + 128
#define SMEM_E_WORDS (SE_OFF + 512)  // 51840
#define SMEM_E_BYTES (SMEM_E_WORDS * 4)  // 207,360

// Scratch (static device globals; no allocation anywhere)
__device__ float g_e[NMAX];
__device__ float g_qry[BMAX * 128];
__device__ float g_m[BMAX];
__device__ float g_rdenom[BMAX];
__device__ __align__(16) unsigned g_Wt[128 * 128];  // tf32-converted W_key

// ---------------------------------------------------------------------------
// helpers
// ---------------------------------------------------------------------------
__device__ __forceinline__ unsigned f2tf(float x) {
    unsigned u;
    asm("cvt.rna.tf32.f32 %0, %1;" : "=r"(u) : "f"(x));
    return u;
}

__device__ __forceinline__ void mma_tf32(float* c, const unsigned* a, const unsigned* b) {
    asm volatile(
        "mma.sync.aligned.m16n8k8.row.col.f32.tf32.tf32.f32 "
        "{%0,%1,%2,%3}, {%4,%5,%6,%7}, {%8,%9}, {%0,%1,%2,%3};"
        : "+f"(c[0]), "+f"(c[1]), "+f"(c[2]), "+f"(c[3])
        : "r"(a[0]), "r"(a[1]), "r"(a[2]), "r"(a[3]),
          "r"(b[0]), "r"(b[1]));
}

__device__ __forceinline__ float fast_sigmoid(float x) {
    float t;
    asm("tanh.approx.f32 %0, %1;" : "=f"(t) : "f"(0.5f * x));
    return 0.5f * t + 0.5f;
}

// ---------------------------------------------------------------------------
// 0) pre-convert W_key to tf32
// ---------------------------------------------------------------------------
__global__ void k_prep(const float* __restrict__ W_key) {
    int i = blockIdx.x * 256 + threadIdx.x;   // 16384 total
    g_Wt[i] = f2tf(W_key[i]);
}

// ---------------------------------------------------------------------------
// 1) qry[b,d] = feat_u[b,:] @ W_user[:,d] + b_user[d]
// ---------------------------------------------------------------------------
__global__ void k_qry(const float* __restrict__ feat_u,
                      const float* __restrict__ W_user,
                      const float* __restrict__ b_user) {
    __shared__ float su[128];
    int b = blockIdx.x, d = threadIdx.x;
    su[d] = feat_u[b * 128 + d];
    __syncthreads();
    float acc = b_user[d];
#pragma unroll 8
    for (int k = 0; k < 128; ++k)
        acc += su[k] * W_user[k * 128 + d];
    g_qry[b * 128 + d] = acc;
}

// no-op padding so ncu (-s 5 -c 1) profiles k_e
__global__ void k_noop() {}

// ---------------------------------------------------------------------------
// 2) e[n] = sum_d sigmoid(qry[seg[n],d] + (feat_i @ W_key)[n,d]) * W_e[d]
//    512 threads; warp w handles 32 rows ((w>>1)*32) x 64 cols ((w&1)*64).
// ---------------------------------------------------------------------------
__global__ __launch_bounds__(512, 1) void k_e(const float* __restrict__ feat_i,
                                              const int* __restrict__ seg,
                                              const float* __restrict__ W_e,
                                              int N) {
    extern __shared__ float smem_f[];
    unsigned* sW  = reinterpret_cast<unsigned*>(smem_f) + SW_OFF;   // [128][136]
    unsigned* sA  = reinterpret_cast<unsigned*>(smem_f) + SA_OFF;   // [256][132]
    float*    sWe = smem_f + SWE_OFF;                                // [128]
    float*    sE  = smem_f + SE_OFF;                                 // [256][2]

    const int tid  = threadIdx.x;
    const int lane = tid & 31;
    const int w    = tid >> 5;
    const int g    = lane >> 2;
    const int qr   = lane & 3;
    const int blockBase = blockIdx.x * EBLK;

    // ---- stage W (already tf32) ----
    {
        const uint4* src = reinterpret_cast<const uint4*>(g_Wt);
        for (int i4 = tid; i4 < 4096; i4 += 512) {
            int r = i4 >> 5, c4 = i4 & 31;
            *reinterpret_cast<uint4*>(sW + r * SW_STRIDE + c4 * 4) = src[i4];
        }
    }
    if (tid < 128) sWe[tid] = W_e[tid];
    // ---- stage A (256 rows feat_i -> tf32) ----
    for (int i4 = tid; i4 < 8192; i4 += 512) {
        int r = i4 >> 5, c4 = i4 & 31;
        int grow = blockBase + r;
        float4 v = (grow < N)
                 ? *reinterpret_cast<const float4*>(&feat_i[(size_t)grow * 128 + c4 * 4])
                 : make_float4(0.f, 0.f, 0.f, 0.f);
        uint4 t;
        t.x = f2tf(v.x); t.y = f2tf(v.y); t.z = f2tf(v.z); t.w = f2tf(v.w);
        *reinterpret_cast<uint4*>(sA + r * SA_STRIDE + c4 * 4) = t;
    }
    __syncthreads();

    const int rg   = w >> 1;        // row group 0..7
    const int c    = w & 1;         // column chunk
    const int wrow = rg * 32;       // local row base

    int sidx[4];
#pragma unroll
    for (int mt = 0; mt < 2; ++mt)
#pragma unroll
        for (int h = 0; h < 2; ++h) {
            int r = blockBase + wrow + mt * 16 + h * 8 + g;
            sidx[mt * 2 + h] = (r < N) ? seg[r] : 0;
        }

    float acc[2][8][4];
#pragma unroll
    for (int mt = 0; mt < 2; ++mt)
#pragma unroll
        for (int nt = 0; nt < 8; ++nt)
#pragma unroll
            for (int i = 0; i < 4; ++i)
                acc[mt][nt][i] = 0.f;

#pragma unroll
    for (int k = 0; k < 16; ++k) {
        unsigned A[2][4];
#pragma unroll
        for (int mt = 0; mt < 2; ++mt) {
            int lr0 = wrow + mt * 16 + g;
            int lr1 = lr0 + 8;
            int c0  = k * 8 + qr;
            A[mt][0] = sA[lr0 * SA_STRIDE + c0];
            A[mt][1] = sA[lr1 * SA_STRIDE + c0];
            A[mt][2] = sA[lr0 * SA_STRIDE + c0 + 4];
            A[mt][3] = sA[lr1 * SA_STRIDE + c0 + 4];
        }
        int kr = k * 8 + qr;
#pragma unroll
        for (int nt = 0; nt < 8; ++nt) {
            unsigned B2[2];
            B2[0] = sW[kr * SW_STRIDE + c * 64 + nt * 8 + g];
            B2[1] = sW[(kr + 4) * SW_STRIDE + c * 64 + nt * 8 + g];
            mma_tf32(acc[0][nt], A[0], B2);
            mma_tf32(acc[1][nt], A[1], B2);
        }
    }

    // epilogue: sigmoid + dot with W_e over this warp's 64 cols
    float epart[4] = {0.f, 0.f, 0.f, 0.f};
#pragma unroll
    for (int mt = 0; mt < 2; ++mt)
#pragma unroll
        for (int nt = 0; nt < 8; ++nt)
#pragma unroll
            for (int i = 0; i < 4; ++i) {
                int col  = c * 64 + nt * 8 + 2 * qr + (i & 1);
                int slot = mt * 2 + (i >> 1);
                float x  = g_qry[sidx[slot] * 128 + col] + acc[mt][nt][i];
                epart[slot] += fast_sigmoid(x) * sWe[col];
            }

#pragma unroll
    for (int j = 0; j < 4; ++j) {
        epart[j] += __shfl_xor_sync(0xffffffffu, epart[j], 1);
        epart[j] += __shfl_xor_sync(0xffffffffu, epart[j], 2);
    }
    if (qr == 0) {
#pragma unroll
        for (int j = 0; j < 4; ++j) {
            int lr = wrow + (j >> 1) * 16 + (j & 1) * 8 + g;
            sE[lr * 2 + c] = epart[j];
        }
    }
    __syncthreads();
    if (tid < 256) {
        int row = blockBase + tid;
        if (row < N) g_e[row] = sE[tid * 2] + sE[tid * 2 + 1];
    }
}

// ---------------------------------------------------------------------------
// 3) per-segment max and 1/sum(exp(e-m)); seg is sorted -> binary search
// ---------------------------------------------------------------------------
__global__ void k_seg(const int* __restrict__ seg, int N) {
    int b = blockIdx.x, tid = threadIdx.x;
    int lo = 0, hi = N;
    while (lo < hi) { int mid = (lo + hi) >> 1; if (seg[mid] < b) lo = mid + 1; else hi = mid; }
    int s0 = lo;
    hi = N;
    while (lo < hi) { int mid = (lo + hi) >> 1; if (seg[mid] < b + 1) lo = mid + 1; else hi = mid; }
    int s1 = lo;

    __shared__ float red[8];
    float mx = -3.402823466e38f;
    for (int i = s0 + tid; i < s1; i += 256) mx = fmaxf(mx, g_e[i]);
#pragma unroll
    for (int o = 16; o; o >>= 1) mx = fmaxf(mx, __shfl_xor_sync(~0u, mx, o));
    if ((tid & 31) == 0) red[tid >> 5] = mx;
    __syncthreads();
    if (tid == 0) {
        float v = red[0];
#pragma unroll
        for (int i = 1; i < 8; ++i) v = fmaxf(v, red[i]);
        red[0] = v;
    }
    __syncthreads();
    float m = red[0];
    __syncthreads();

    float sm = 0.f;
    for (int i = s0 + tid; i < s1; i += 256) sm += __expf(g_e[i] - m);
#pragma unroll
    for (int o = 16; o; o >>= 1) sm += __shfl_xor_sync(~0u, sm, o);
    if ((tid & 31) == 0) red[tid >> 5] = sm;
    __syncthreads();
    if (tid == 0) {
        float t = 0.f;
#pragma unroll
        for (int i = 0; i < 8; ++i) t += red[i];
        g_m[b]      = (s1 > s0) ? m : 0.f;
        g_rdenom[b] = (s1 > s0) ? __fdividef(1.f, t) : 1.f;
    }
}

// ---------------------------------------------------------------------------
// 4) rst[b,:] += alpha[n] * feat_i[n,:]; alpha inline, pipelined loads
// ---------------------------------------------------------------------------
__global__ __launch_bounds__(256) void k_out(const float* __restrict__ feat_i,
                                             const int* __restrict__ seg,
                                             float* __restrict__ out, int N) {
    const int lane = threadIdx.x & 31;
    const int wj   = threadIdx.x >> 5;
    long start = (long)blockIdx.x * NPB;
    long end   = start + NPB;
    if (end > N) end = N;
    long n0 = start + wj;
    if (n0 >= end) return;

    float4 acc = make_float4(0.f, 0.f, 0.f, 0.f);
    int   cur = seg[n0];
    int   s   = cur;
    float e   = g_e[n0];
    float4 v  = *reinterpret_cast<const float4*>(&feat_i[n0 * 128 + lane * 4]);

    for (long n = n0; n < end; n += 8) {
        long n2 = n + 8;
        int s2 = 0; float e2 = 0.f;
        float4 v2 = make_float4(0.f, 0.f, 0.f, 0.f);
        if (n2 < end) {
            s2 = seg[n2];
            e2 = g_e[n2];
            v2 = *reinterpret_cast<const float4*>(&feat_i[n2 * 128 + lane * 4]);
        }
        float al = __expf(e - g_m[s]) * g_rdenom[s];
        if (s != cur) {
            float* o = &out[cur * 128 + lane * 4];
            atomicAdd(o + 0, acc.x); atomicAdd(o + 1, acc.y);
            atomicAdd(o + 2, acc.z); atomicAdd(o + 3, acc.w);
            acc = make_float4(0.f, 0.f, 0.f, 0.f);
            cur = s;
        }
        acc.x += al * v.x; acc.y += al * v.y;
        acc.z += al * v.z; acc.w += al * v.w;
        s = s2; e = e2; v = v2;
    }
    float* o = &out[cur * 128 + lane * 4];
    atomicAdd(o + 0, acc.x); atomicAdd(o + 1, acc.y);
    atomicAdd(o + 2, acc.z); atomicAdd(o + 3, acc.w);
}

// ---------------------------------------------------------------------------
extern "C" void kernel_launch(void* const* d_in, const int* in_sizes, int n_in,
                              void* d_out, int out_size) {
    const float* feat_i = (const float*)d_in[0];
    const float* feat_u = (const float*)d_in[1];
    const int*   seg    = (const int*)d_in[2];
    const float* W_key  = (const float*)d_in[3];
    const float* W_user = (const float*)d_in[4];
    const float* b_user = (const float*)d_in[5];
    const float* W_e    = (const float*)d_in[6];
    float* out = (float*)d_out;

    int N = in_sizes[0] / 128;
    int B = in_sizes[1] / 128;

    cudaFuncSetAttribute(k_e, cudaFuncAttributeMaxDynamicSharedMemorySize,
                         SMEM_E_BYTES);

    k_prep<<<64, 256>>>(W_key);                 // launch idx 0
    k_qry<<<B, 128>>>(feat_u, W_user, b_user);  // idx 1
    k_noop<<<1, 32>>>();                        // idx 2
    k_noop<<<1, 32>>>();                        // idx 3
    k_noop<<<1, 32>>>();                        // idx 4
    k_e<<<(N + EBLK - 1) / EBLK, 512, SMEM_E_BYTES>>>(feat_i, seg, W_e, N);  // idx 5
    k_seg<<<B, 256>>>(seg, N);
    cudaMemsetAsync(d_out, 0, (size_t)out_size * sizeof(float), 0);
    k_out<<<(N + NPB - 1) / NPB, 256>>>(feat_i, seg, out, N);
}

// round 6
// speedup vs baseline: 2.1257x; 1.1758x over previous
#include <cuda_runtime.h>
#include <cuda_fp16.h>
#include <cstdint>

#define NMAX (1 << 20)   // >= 1,000,000 nodes
#define BMAX 512         // >= 256 graphs
#define NPB  256         // nodes per block in k_out
#define EBLK 256         // rows per block in k_e

// k_e shared memory layout in 4-byte words (half2 granularity)
#define STR 68                       // row stride (words) for sW and sA
#define SW_OFF 0                     // [128][68]  W^T half2: {W[2k][n],W[2k+1][n]}
#define SA_OFF 8704                  // [256][68]  A half2 (row-major cols packed)
#define SWE_OFF 26112                // [128] float W_e
#define SE_OFF 26240                 // [256][2] float partial e
#define SMEM_E_WORDS (SE_OFF + 512)  // 26752
#define SMEM_E_BYTES (SMEM_E_WORDS * 4)  // 107,008

// Scratch (static device globals; no allocation anywhere)
__device__ float g_e[NMAX];
__device__ float g_qry[BMAX * 128];
__device__ float g_m[BMAX];
__device__ float g_rdenom[BMAX];
__device__ __align__(16) unsigned g_Wth2[128 * 64];  // transposed half2 W_key image

// ---------------------------------------------------------------------------
// helpers
// ---------------------------------------------------------------------------
__device__ __forceinline__ void mma_f16(float* c, const unsigned* a, const unsigned* b) {
    asm volatile(
        "mma.sync.aligned.m16n8k16.row.col.f32.f16.f16.f32 "
        "{%0,%1,%2,%3}, {%4,%5,%6,%7}, {%8,%9}, {%0,%1,%2,%3};"
        : "+f"(c[0]), "+f"(c[1]), "+f"(c[2]), "+f"(c[3])
        : "r"(a[0]), "r"(a[1]), "r"(a[2]), "r"(a[3]),
          "r"(b[0]), "r"(b[1]));
}

__device__ __forceinline__ float fast_sigmoid(float x) {
    float t;
    asm("tanh.approx.f32 %0, %1;" : "=f"(t) : "f"(0.5f * x));
    return 0.5f * t + 0.5f;
}

__device__ __forceinline__ unsigned pack_h2(float a, float b) {
    __half2 h = __floats2half2_rn(a, b);
    return *reinterpret_cast<unsigned*>(&h);
}

// ---------------------------------------------------------------------------
// 0) build transposed half2 W image: g_Wth2[n*64 + k2] = {W[2k2][n], W[2k2+1][n]}
// ---------------------------------------------------------------------------
__global__ void k_prep(const float* __restrict__ W_key) {
    int i = blockIdx.x * 256 + threadIdx.x;   // 8192 total
    int n = i >> 6, k2 = i & 63;
    g_Wth2[i] = pack_h2(W_key[(2 * k2) * 128 + n], W_key[(2 * k2 + 1) * 128 + n]);
}

// ---------------------------------------------------------------------------
// 1) qry[b,d] = feat_u[b,:] @ W_user[:,d] + b_user[d]
// ---------------------------------------------------------------------------
__global__ void k_qry(const float* __restrict__ feat_u,
                      const float* __restrict__ W_user,
                      const float* __restrict__ b_user) {
    __shared__ float su[128];
    int b = blockIdx.x, d = threadIdx.x;
    su[d] = feat_u[b * 128 + d];
    __syncthreads();
    float acc = b_user[d];
#pragma unroll 8
    for (int k = 0; k < 128; ++k)
        acc += su[k] * W_user[k * 128 + d];
    g_qry[b * 128 + d] = acc;
}

// no-op padding so ncu (-s 5 -c 1) lands on k_e
__global__ void k_noop() {}

// ---------------------------------------------------------------------------
// 2) e[n] = sum_d sigmoid(qry[seg[n],d] + (feat_i @ W_key)[n,d]) * W_e[d]
//    fp16 m16n8k16 mma (tf32-class mantissa, half the instructions).
//    512 threads; warp w: rows (w>>1)*32, cols (w&1)*64.
// ---------------------------------------------------------------------------
__global__ __launch_bounds__(512, 1) void k_e(const float* __restrict__ feat_i,
                                              const int* __restrict__ seg,
                                              const float* __restrict__ W_e,
                                              int N) {
    extern __shared__ unsigned smem_u[];
    unsigned* sW  = smem_u + SW_OFF;                       // [128][STR]
    unsigned* sA  = smem_u + SA_OFF;                       // [256][STR]
    float*    sWe = reinterpret_cast<float*>(smem_u + SWE_OFF);
    float*    sE  = reinterpret_cast<float*>(smem_u + SE_OFF);

    const int tid  = threadIdx.x;
    const int lane = tid & 31;
    const int w    = tid >> 5;
    const int g    = lane >> 2;
    const int qr   = lane & 3;
    const int blockBase = blockIdx.x * EBLK;

    // ---- stage W^T image (plain vectorized copy) ----
    {
        const uint4* src = reinterpret_cast<const uint4*>(g_Wth2);
        for (int i4 = tid; i4 < 2048; i4 += 512) {
            int n = i4 >> 4, c4 = i4 & 15;
            *reinterpret_cast<uint4*>(sW + n * STR + c4 * 4) = src[i4];
        }
    }
    if (tid < 128) sWe[tid] = W_e[tid];
    // ---- stage A: 256 rows feat_i -> half2 ----
    for (int i4 = tid; i4 < 8192; i4 += 512) {
        int r = i4 >> 5, c4 = i4 & 31;
        int grow = blockBase + r;
        float4 v = (grow < N)
                 ? *reinterpret_cast<const float4*>(&feat_i[(size_t)grow * 128 + c4 * 4])
                 : make_float4(0.f, 0.f, 0.f, 0.f);
        uint2 t;
        t.x = pack_h2(v.x, v.y);
        t.y = pack_h2(v.z, v.w);
        *reinterpret_cast<uint2*>(sA + r * STR + c4 * 2) = t;
    }
    __syncthreads();

    const int rg   = w >> 1;
    const int c    = w & 1;
    const int wrow = rg * 32;

    int sidx[4];
#pragma unroll
    for (int mt = 0; mt < 2; ++mt)
#pragma unroll
        for (int h = 0; h < 2; ++h) {
            int r = blockBase + wrow + mt * 16 + h * 8 + g;
            sidx[mt * 2 + h] = (r < N) ? seg[r] : 0;
        }

    float acc[2][8][4];
#pragma unroll
    for (int mt = 0; mt < 2; ++mt)
#pragma unroll
        for (int nt = 0; nt < 8; ++nt)
#pragma unroll
            for (int i = 0; i < 4; ++i)
                acc[mt][nt][i] = 0.f;

#pragma unroll
    for (int ks = 0; ks < 8; ++ks) {
        unsigned A[2][4];
#pragma unroll
        for (int mt = 0; mt < 2; ++mt) {
            int lr0 = wrow + mt * 16 + g;
            int lr1 = lr0 + 8;
            int c0  = ks * 8 + qr;
            A[mt][0] = sA[lr0 * STR + c0];       // A[g][2qr..2qr+1]
            A[mt][1] = sA[lr1 * STR + c0];       // A[g+8][...]
            A[mt][2] = sA[lr0 * STR + c0 + 4];   // A[g][2qr+8..]
            A[mt][3] = sA[lr1 * STR + c0 + 4];
        }
#pragma unroll
        for (int nt = 0; nt < 8; ++nt) {
            int n = c * 64 + nt * 8 + g;
            unsigned B2[2];
            B2[0] = sW[n * STR + ks * 8 + qr];       // {B[2qr][n],B[2qr+1][n]}
            B2[1] = sW[n * STR + ks * 8 + qr + 4];   // {B[2qr+8][n],B[2qr+9][n]}
            mma_f16(acc[0][nt], A[0], B2);
            mma_f16(acc[1][nt], A[1], B2);
        }
    }

    // epilogue: sigmoid + dot with W_e over this warp's 64 cols
    float epart[4] = {0.f, 0.f, 0.f, 0.f};
#pragma unroll
    for (int mt = 0; mt < 2; ++mt)
#pragma unroll
        for (int nt = 0; nt < 8; ++nt)
#pragma unroll
            for (int i = 0; i < 4; ++i) {
                int col  = c * 64 + nt * 8 + 2 * qr + (i & 1);
                int slot = mt * 2 + (i >> 1);
                float x  = g_qry[sidx[slot] * 128 + col] + acc[mt][nt][i];
                epart[slot] += fast_sigmoid(x) * sWe[col];
            }

#pragma unroll
    for (int j = 0; j < 4; ++j) {
        epart[j] += __shfl_xor_sync(0xffffffffu, epart[j], 1);
        epart[j] += __shfl_xor_sync(0xffffffffu, epart[j], 2);
    }
    if (qr == 0) {
#pragma unroll
        for (int j = 0; j < 4; ++j) {
            int lr = wrow + (j >> 1) * 16 + (j & 1) * 8 + g;
            sE[lr * 2 + c] = epart[j];
        }
    }
    __syncthreads();
    if (tid < 256) {
        int row = blockBase + tid;
        if (row < N) g_e[row] = sE[tid * 2] + sE[tid * 2 + 1];
    }
}

// ---------------------------------------------------------------------------
// 3) per-segment max and 1/sum(exp(e-m)); seg is sorted -> binary search
// ---------------------------------------------------------------------------
__global__ void k_seg(const int* __restrict__ seg, int N) {
    int b = blockIdx.x, tid = threadIdx.x;
    int lo = 0, hi = N;
    while (lo < hi) { int mid = (lo + hi) >> 1; if (seg[mid] < b) lo = mid + 1; else hi = mid; }
    int s0 = lo;
    hi = N;
    while (lo < hi) { int mid = (lo + hi) >> 1; if (seg[mid] < b + 1) lo = mid + 1; else hi = mid; }
    int s1 = lo;

    __shared__ float red[8];
    float mx = -3.402823466e38f;
    for (int i = s0 + tid; i < s1; i += 256) mx = fmaxf(mx, g_e[i]);
#pragma unroll
    for (int o = 16; o; o >>= 1) mx = fmaxf(mx, __shfl_xor_sync(~0u, mx, o));
    if ((tid & 31) == 0) red[tid >> 5] = mx;
    __syncthreads();
    if (tid == 0) {
        float v = red[0];
#pragma unroll
        for (int i = 1; i < 8; ++i) v = fmaxf(v, red[i]);
        red[0] = v;
    }
    __syncthreads();
    float m = red[0];
    __syncthreads();

    float sm = 0.f;
    for (int i = s0 + tid; i < s1; i += 256) sm += __expf(g_e[i] - m);
#pragma unroll
    for (int o = 16; o; o >>= 1) sm += __shfl_xor_sync(~0u, sm, o);
    if ((tid & 31) == 0) red[tid >> 5] = sm;
    __syncthreads();
    if (tid == 0) {
        float t = 0.f;
#pragma unroll
        for (int i = 0; i < 8; ++i) t += red[i];
        g_m[b]      = (s1 > s0) ? m : 0.f;
        g_rdenom[b] = (s1 > s0) ? __fdividef(1.f, t) : 1.f;
    }
}

// ---------------------------------------------------------------------------
// 4) rst[b,:] += alpha[n] * feat_i[n,:]; alpha inline, pipelined loads
// ---------------------------------------------------------------------------
__global__ __launch_bounds__(256) void k_out(const float* __restrict__ feat_i,
                                             const int* __restrict__ seg,
                                             float* __restrict__ out, int N) {
    const int lane = threadIdx.x & 31;
    const int wj   = threadIdx.x >> 5;
    long start = (long)blockIdx.x * NPB;
    long end   = start + NPB;
    if (end > N) end = N;
    long n0 = start + wj;
    if (n0 >= end) return;

    float4 acc = make_float4(0.f, 0.f, 0.f, 0.f);
    int   cur = seg[n0];
    int   s   = cur;
    float e   = g_e[n0];
    float4 v  = *reinterpret_cast<const float4*>(&feat_i[n0 * 128 + lane * 4]);

    for (long n = n0; n < end; n += 8) {
        long n2 = n + 8;
        int s2 = 0; float e2 = 0.f;
        float4 v2 = make_float4(0.f, 0.f, 0.f, 0.f);
        if (n2 < end) {
            s2 = seg[n2];
            e2 = g_e[n2];
            v2 = *reinterpret_cast<const float4*>(&feat_i[n2 * 128 + lane * 4]);
        }
        float al = __expf(e - g_m[s]) * g_rdenom[s];
        if (s != cur) {
            float* o = &out[cur * 128 + lane * 4];
            atomicAdd(o + 0, acc.x); atomicAdd(o + 1, acc.y);
            atomicAdd(o + 2, acc.z); atomicAdd(o + 3, acc.w);
            acc = make_float4(0.f, 0.f, 0.f, 0.f);
            cur = s;
        }
        acc.x += al * v.x; acc.y += al * v.y;
        acc.z += al * v.z; acc.w += al * v.w;
        s = s2; e = e2; v = v2;
    }
    float* o = &out[cur * 128 + lane * 4];
    atomicAdd(o + 0, acc.x); atomicAdd(o + 1, acc.y);
    atomicAdd(o + 2, acc.z); atomicAdd(o + 3, acc.w);
}

// ---------------------------------------------------------------------------
extern "C" void kernel_launch(void* const* d_in, const int* in_sizes, int n_in,
                              void* d_out, int out_size) {
    const float* feat_i = (const float*)d_in[0];
    const float* feat_u = (const float*)d_in[1];
    const int*   seg    = (const int*)d_in[2];
    const float* W_key  = (const float*)d_in[3];
    const float* W_user = (const float*)d_in[4];
    const float* b_user = (const float*)d_in[5];
    const float* W_e    = (const float*)d_in[6];
    float* out = (float*)d_out;

    int N = in_sizes[0] / 128;
    int B = in_sizes[1] / 128;

    cudaFuncSetAttribute(k_e, cudaFuncAttributeMaxDynamicSharedMemorySize,
                         SMEM_E_BYTES);

    k_prep<<<32, 256>>>(W_key);                 // idx 0
    k_qry<<<B, 128>>>(feat_u, W_user, b_user);  // idx 1
    k_noop<<<1, 32>>>();                        // idx 2
    k_noop<<<1, 32>>>();                        // idx 3
    k_e<<<(N + EBLK - 1) / EBLK, 512, SMEM_E_BYTES>>>(feat_i, seg, W_e, N);  // idx 4
    k_seg<<<B, 256>>>(seg, N);
    cudaMemsetAsync(d_out, 0, (size_t)out_size * sizeof(float), 0);
    k_out<<<(N + NPB - 1) / NPB, 256>>>(feat_i, seg, out, N);
}